// round 16
// baseline (speedup 1.0000x reference)
#include <cuda_runtime.h>
#include <cuda_bf16.h>
#include <mma.h>
#include <math.h>
#include <stdint.h>

using namespace nvcuda;

#define NN   25000
#define NE   500000
#define NDIM 32
#define EDIM 19
#define GG   200

// ---- tensor-GEMM geometry ---------------------------------------------------
#define NTILE 196                 // M-tiles of 128 nodes
#define KP    208                 // K padded (weight planes)
#define NT    13                  // output 16-col tiles (208)
#define APL   (128 * 24)          // smem A plane (elements)
#define BPL   (208 * 24)          // smem B plane (elements)
#define WPL   ((size_t)KP * KP)   // global W plane per slice (elements)

// ---------------- scratch (device globals) ----------------------------------
static __device__ float g_hv[NN * GG];
static __device__ float g_P[NN * GG];
static __device__ float g_q[NN];
static __device__ float g_denom[NN];
static __device__ float g_s[NN * GG];
static __device__ float g_ctx[NN * GG];
static __device__ float g_gates[(size_t)4 * NN * GG];   // r-sum, z-sum, inn, hn
static __device__ __align__(128) __nv_bfloat16 g_Wpk[7 * 2 * KP * KP];

// ---------------- helpers ----------------------------------------------------
__device__ __forceinline__ float lrelu(float x) { return x > 0.f ? x : 0.01f * x; }
__device__ __forceinline__ float sigm(float x) { return 1.f / (1.f + __expf(-x)); }
__device__ __forceinline__ void bfsplit(float x, __nv_bfloat16& hi, __nv_bfloat16& lo) {
    hi = __float2bfloat16(x);
    lo = __float2bfloat16(x - __bfloat162float(hi));
}
__device__ __forceinline__ unsigned pack2(__nv_bfloat16 a, __nv_bfloat16 b) {
    return (unsigned)__bfloat16_as_ushort(a) | ((unsigned)__bfloat16_as_ushort(b) << 16);
}
// NOTE: no "memory" clobber — g_s is never read in this kernel; register
// data-deps order value production; volatile keeps the reds themselves.
__device__ __forceinline__ void red4(float* p, float a, float b, float c, float d) {
    asm volatile("red.global.add.v4.f32 [%0], {%1, %2, %3, %4};"
                 :: "l"(p), "f"(a), "f"(b), "f"(c), "f"(d));
}

// ---------------- k_init (vectorized) ----------------------------------------
__global__ void k_init() {
    int idx = blockIdx.x * blockDim.x + threadIdx.x;
    if (idx < NN * GG / 4)
        ((float4*)g_s)[idx] = make_float4(0.f, 0.f, 0.f, 0.f);
    if (idx < NN) g_denom[idx] = 0.f;
}

// ---------------- k_packW ------------------------------------------------------
__global__ void k_packW(const float* __restrict__ Wet,
                        const float* __restrict__ Wih,
                        const float* __restrict__ Whh) {
    int idx = blockIdx.x * 256 + threadIdx.x;
    if (idx >= 7 * KP * KP) return;
    int s = idx / (KP * KP);
    int rem = idx - s * (KP * KP);
    int n = rem / KP, k = rem - n * KP;
    float v = 0.f;
    if (n < GG && k < GG) {
        if (s == 0)       v = Wet[n * GG + k];
        else if (s < 4)   v = Wih[(size_t)((s - 1) * GG + n) * GG + k];
        else              v = Whh[(size_t)((s - 4) * GG + n) * GG + k];
    }
    __nv_bfloat16 hi, lo; bfsplit(v, hi, lo);
    g_Wpk[(size_t)(s * 2) * KP * KP + rem] = hi;
    g_Wpk[(size_t)(s * 2 + 1) * KP * KP + rem] = lo;
}

// ---------------- k_nodeproj ---------------------------------------------------
#define NP_WNT  0
#define NP_W1T  7296
#define NP_INS  14592
#define NP_BN   15648
#define NP_W2A  15848
#define NP_QP   16048
#define NP_SMEM 16304

__global__ void k_nodeproj(const float* __restrict__ nf,
                           const float* __restrict__ Wn,
                           const float* __restrict__ bn,
                           const float* __restrict__ We2,
                           const float* __restrict__ We1) {
    extern __shared__ float sm[];
    float* wnt  = sm + NP_WNT;
    float* w1t  = sm + NP_W1T;
    float* ins  = sm + NP_INS;
    float* bn_s = sm + NP_BN;
    float* w2a  = sm + NP_W2A;
    float* qp   = sm + NP_QP;
    float* outh = sm;
    float* outp = sm + 6432;

    int tid = threadIdx.x;
    int lane = tid & 31, grp = tid >> 5;
    int n0 = blockIdx.x * 32;

    for (int i = tid; i < GG * NDIM; i += 256) {
        int r = i >> 5, k = i & 31;
        int g = r / 25, j = r - g * 25;
        wnt[k * 228 + g * 28 + j] = Wn[i];
        w1t[k * 228 + g * 28 + j] = We1[r * 51 + k];
    }
    for (int i = tid; i < GG; i += 256) { bn_s[i] = bn[i]; w2a[i] = We2[i]; }
    for (int i = tid; i < 32 * NDIM; i += 256) {
        int n = i >> 5, k = i & 31;
        ins[k * 33 + n] = (n0 + n < NN) ? nf[(size_t)(n0 + n) * NDIM + k] : 0.f;
    }
    __syncthreads();

    float acc[28], accP[28];
#pragma unroll
    for (int j = 0; j < 28; j++) { acc[j] = (j < 25) ? bn_s[grp * 25 + j] : 0.f; accP[j] = 0.f; }

    for (int k = 0; k < NDIM; k++) {
        float x = ins[k * 33 + lane];
        const float4* wp = (const float4*)&wnt[k * 228 + grp * 28];
        const float4* pp = (const float4*)&w1t[k * 228 + grp * 28];
#pragma unroll
        for (int j4 = 0; j4 < 7; j4++) {
            float4 w = wp[j4], p = pp[j4];
            acc[j4*4+0] += x * w.x;  acc[j4*4+1] += x * w.y;
            acc[j4*4+2] += x * w.z;  acc[j4*4+3] += x * w.w;
            accP[j4*4+0] += x * p.x; accP[j4*4+1] += x * p.y;
            accP[j4*4+2] += x * p.z; accP[j4*4+3] += x * p.w;
        }
    }
    __syncthreads();

    float qdot = 0.f;
#pragma unroll
    for (int j = 0; j < 25; j++) {
        float v = lrelu(acc[j]);
        outh[lane * 201 + grp * 25 + j] = v;
        outp[lane * 201 + grp * 25 + j] = accP[j];
        qdot += v * w2a[grp * 25 + j];
    }
    qp[grp * 32 + lane] = qdot;
    __syncthreads();

    for (int i = tid; i < 32 * GG; i += 256) {
        int n = i / GG, o = i - n * GG;
        if (n0 + n < NN) {
            g_hv[(size_t)(n0 + n) * GG + o] = outh[n * 201 + o];
            g_P[(size_t)(n0 + n) * GG + o]  = outp[n * 201 + o];
        }
    }
    if (tid < 32 && n0 + tid < NN) {
        float q = 0.f;
#pragma unroll
        for (int g = 0; g < 8; g++) q += qp[g * 32 + tid];
        g_q[n0 + tid] = q;
    }
}

// ---------------- k_edge1: warp-per-edge, phase-split epilogue -----------------
#define E_NT   (NE / 32)

__global__ void __launch_bounds__(256)
k_edge1(const float* __restrict__ ef,
        const int* __restrict__ src,
        const int* __restrict__ dst,
        const float* __restrict__ We1,
        const float* __restrict__ be1,
        const float* __restrict__ We2,
        const float* __restrict__ be2) {
    __shared__ float w1s[19 * 256];
    __shared__ float b1s[256];
    __shared__ float w2bs[256];

    int tid = threadIdx.x;
    int lane = tid & 31, warp = tid >> 5;
    const unsigned FULL = 0xffffffffu;

    for (int i = tid; i < 19 * 256; i += 256) {
        int k = i >> 8, f = i & 255;
        w1s[i] = (f < GG) ? We1[f * 51 + NDIM + k] : 0.f;
    }
    for (int i = tid; i < 256; i += 256) {
        b1s[i]  = (i < GG) ? be1[i] : 0.f;
        w2bs[i] = (i < GG) ? We2[GG + i] : 0.f;
    }
    float be2v = be2[0];
    __syncthreads();

    float4 binit0 = *(const float4*)&b1s[lane * 4];
    float4 binit1 = *(const float4*)&b1s[128 + lane * 4];
    float4 w2r0   = *(const float4*)&w2bs[lane * 4];
    float4 w2r1   = *(const float4*)&w2bs[128 + lane * 4];
    bool q1ok = (lane < 18);

    for (int t = blockIdx.x; t < E_NT; t += gridDim.x) {
        int ebase = t * 32 + warp * 4;

        int sreg = 0, dreg = 0;
        if (lane < 4) { sreg = src[ebase + lane]; dreg = dst[ebase + lane]; }
        float er[4];
#pragma unroll
        for (int q = 0; q < 4; q++)
            er[q] = (lane < EDIM) ? ef[(size_t)(ebase + q) * EDIM + lane] : 0.f;

        float acc[4][8];
#pragma unroll
        for (int q = 0; q < 4; q++) {
            acc[q][0] = binit0.x; acc[q][1] = binit0.y;
            acc[q][2] = binit0.z; acc[q][3] = binit0.w;
            acc[q][4] = binit1.x; acc[q][5] = binit1.y;
            acc[q][6] = binit1.z; acc[q][7] = binit1.w;
        }

        for (int k = 0; k < EDIM; k++) {
            float4 w0 = *(const float4*)&w1s[k * 256 + lane * 4];
            float4 w1 = *(const float4*)&w1s[k * 256 + 128 + lane * 4];
#pragma unroll
            for (int q = 0; q < 4; q++) {
                float x = __shfl_sync(FULL, er[q], k);
                acc[q][0] += x * w0.x; acc[q][1] += x * w0.y;
                acc[q][2] += x * w0.z; acc[q][3] += x * w0.w;
                acc[q][4] += x * w1.x; acc[q][5] += x * w1.y;
                acc[q][6] += x * w1.z; acc[q][7] += x * w1.w;
            }
        }

        // ---- phase A: loads + he1 + logits (no global stores -> MLP across q) --
        float exq[4];
#pragma unroll
        for (int q = 0; q < 4; q++) {
            int s_q = __shfl_sync(FULL, sreg, q);
            const float* Pr = g_P + (size_t)s_q * GG;

            float4 p0 = *(const float4*)(Pr + lane * 4);
            float4 p1 = q1ok ? *(const float4*)(Pr + 128 + lane * 4)
                             : make_float4(0.f, 0.f, 0.f, 0.f);

            float v0 = lrelu(acc[q][0] + p0.x);
            float v1 = lrelu(acc[q][1] + p0.y);
            float v2 = lrelu(acc[q][2] + p0.z);
            float v3 = lrelu(acc[q][3] + p0.w);
            float v4 = lrelu(acc[q][4] + p1.x);
            float v5 = lrelu(acc[q][5] + p1.y);
            float v6 = lrelu(acc[q][6] + p1.z);
            float v7 = lrelu(acc[q][7] + p1.w);
            acc[q][0] = v0; acc[q][1] = v1; acc[q][2] = v2; acc[q][3] = v3;
            acc[q][4] = v4; acc[q][5] = v5; acc[q][6] = v6; acc[q][7] = v7;

            float p = v0 * w2r0.x + v1 * w2r0.y + v2 * w2r0.z + v3 * w2r0.w
                    + v4 * w2r1.x + v5 * w2r1.y + v6 * w2r1.z + v7 * w2r1.w;
            p += __shfl_xor_sync(FULL, p, 16);
            p += __shfl_xor_sync(FULL, p, 8);
            p += __shfl_xor_sync(FULL, p, 4);
            p += __shfl_xor_sync(FULL, p, 2);
            p += __shfl_xor_sync(FULL, p, 1);

            int d_q = __shfl_sync(FULL, dreg, q);
            float l = lrelu(be2v + g_q[d_q] + p);
            exq[q] = __expf(l);               // unnormalized softmax
        }

        // ---- phase B: atomics + scatters ---------------------------------------
#pragma unroll
        for (int q = 0; q < 4; q++) {
            int d_q = __shfl_sync(FULL, dreg, q);
            float ex = exq[q];
            if (lane == q) atomicAdd(&g_denom[d_q], ex);
            float* drow = g_s + (size_t)d_q * GG;
            red4(drow + lane * 4,
                 ex * acc[q][0], ex * acc[q][1], ex * acc[q][2], ex * acc[q][3]);
            if (q1ok)
                red4(drow + 128 + lane * 4,
                     ex * acc[q][4], ex * acc[q][5], ex * acc[q][6], ex * acc[q][7]);
        }
    }
}

// ---------------- k_wmma: double-buffered, vectorized-staging bf16-split GEMM --
// MODE 0 (grid 196):  ctx = elu(Wet @ (s/denom) + has*bet) -> g_ctx fp32
// MODE 1 (grid 196x4): y=0 r-sum K=416 [ctx;hv], y=1 z-sum K=416,
//                      y=2 inn = Wih_n@ctx, y=3 hn = Whh_n@hv
#define WAS(buf)  ((buf) * 12288)
#define WBS(buf)  (24576 + (buf) * 19968)
#define WPATCH    64512
#define WBIAS     74752
#define WM_SMEM   75584

template <int MODE>
__global__ void __launch_bounds__(256)
k_wmma(const float* __restrict__ bias_a, const float* __restrict__ bias_b) {
    extern __shared__ unsigned char smraw[];
    float* patch  = (float*)(smraw + WPATCH);
    float* bias_s = (float*)(smraw + WBIAS);

    int tid = threadIdx.x, lane = tid & 31, warp = tid >> 5;
    int tile = blockIdx.x;
    int y = (MODE == 0) ? 0 : blockIdx.y;
    int KTOT = (MODE == 0) ? 13 : ((y < 2) ? 26 : 13);

    for (int i = tid; i < KP; i += 256) {
        float b = 0.f;
        if (i < GG) {
            if (MODE == 0)      b = bias_a[i];
            else if (y == 0)    b = bias_a[i] + bias_b[i];
            else if (y == 1)    b = bias_a[GG + i] + bias_b[GG + i];
            else if (y == 2)    b = bias_a[2 * GG + i];
            else                b = bias_b[2 * GG + i];
        }
        bias_s[i] = b;
    }

    auto stage = [&](int kt, int buf) {
        int ktt = kt, slice; const float* srcA; bool use_inv = false;
        if (MODE == 0) { slice = 0; srcA = g_s; use_inv = true; }
        else if (y < 2) {
            if (kt < 13) { slice = 1 + y; srcA = g_ctx; }
            else         { slice = 4 + y; srcA = g_hv; ktt = kt - 13; }
        } else if (y == 2) { slice = 3; srcA = g_ctx; }
        else               { slice = 6; srcA = g_hv; }

        unsigned char* Asb = smraw + WAS(buf);
        unsigned char* Bsb = smraw + WBS(buf);
        const __nv_bfloat16* Wh = g_Wpk + (size_t)(slice * 2) * WPL;

        for (int i = tid; i < 512; i += 256) {
            int r = i >> 2, qd = i & 3;
            int node = tile * 128 + r;
            int kk = ktt * 16 + qd * 4;
            float4 v = make_float4(0.f, 0.f, 0.f, 0.f);
            if (node < NN && kk < GG) {
                v = *(const float4*)(srcA + (size_t)node * GG + kk);
                if (use_inv) {
                    float dn = g_denom[node];
                    float iv = (dn > 0.f) ? (1.f / dn) : 0.f;
                    v.x *= iv; v.y *= iv; v.z *= iv; v.w *= iv;
                }
            }
            __nv_bfloat16 h0, l0, h1, l1, h2, l2, h3, l3;
            bfsplit(v.x, h0, l0); bfsplit(v.y, h1, l1);
            bfsplit(v.z, h2, l2); bfsplit(v.w, h3, l3);
            uint2 hv2 = make_uint2(pack2(h0, h1), pack2(h2, h3));
            uint2 lv2 = make_uint2(pack2(l0, l1), pack2(l2, l3));
            *(uint2*)(Asb + r * 48 + qd * 8) = hv2;
            *(uint2*)(Asb + APL * 2 + r * 48 + qd * 8) = lv2;
        }
        for (int i = tid; i < 832; i += 256) {
            int n = i >> 2, q = i & 3;
            int plane = q >> 1, half = q & 1;
            const uint4* srcp = (const uint4*)((const unsigned char*)(Wh + (size_t)plane * WPL)
                                               + (size_t)n * (KP * 2) + ktt * 32 + half * 16);
            *(uint4*)(Bsb + (size_t)plane * (BPL * 2) + n * 48 + half * 16) = *srcp;
        }
    };

    wmma::fragment<wmma::accumulator, 16, 16, 16, float> acc[NT];
#pragma unroll
    for (int nt = 0; nt < NT; nt++) wmma::fill_fragment(acc[nt], 0.f);

    stage(0, 0);
    __syncthreads();

    for (int kt = 0; kt < KTOT; kt++) {
        int cur = kt & 1;
        if (kt + 1 < KTOT) stage(kt + 1, cur ^ 1);

        __nv_bfloat16* As = (__nv_bfloat16*)(smraw + WAS(cur));
        __nv_bfloat16* Bs = (__nv_bfloat16*)(smraw + WBS(cur));

        wmma::fragment<wmma::matrix_a, 16, 16, 16, __nv_bfloat16, wmma::row_major> a_hi, a_lo;
        wmma::load_matrix_sync(a_hi, As + warp * 16 * 24, 24);
        wmma::load_matrix_sync(a_lo, As + APL + warp * 16 * 24, 24);
#pragma unroll
        for (int nt = 0; nt < NT; nt++) {
            wmma::fragment<wmma::matrix_b, 16, 16, 16, __nv_bfloat16, wmma::col_major> b_hi, b_lo;
            wmma::load_matrix_sync(b_hi, Bs + nt * 16 * 24, 24);
            wmma::load_matrix_sync(b_lo, Bs + BPL + nt * 16 * 24, 24);
            wmma::mma_sync(acc[nt], a_hi, b_hi, acc[nt]);
            wmma::mma_sync(acc[nt], a_hi, b_lo, acc[nt]);
            wmma::mma_sync(acc[nt], a_lo, b_hi, acc[nt]);
        }
        __syncthreads();
    }

    float* pp = patch + warp * (16 * 20);
    int rr = lane >> 1;
    int c0 = (lane & 1) * 8;
    int mrow = tile * 128 + warp * 16 + rr;
    bool valid = mrow < NN;
    float hasb = 0.f;
    if (MODE == 0) hasb = (valid && g_denom[mrow] > 0.f) ? 1.f : 0.f;

    for (int nt = 0; nt < NT; nt++) {
        wmma::store_matrix_sync(pp, acc[nt], 20, wmma::mem_row_major);
        __syncwarp();
        int jb = nt * 16 + c0;
        if (valid && jb + 8 <= GG) {
            const float* pr = pp + rr * 20 + c0;
            if (MODE == 0) {
                float* cp = g_ctx + (size_t)mrow * GG + jb;
                float o[8];
#pragma unroll
                for (int i = 0; i < 8; i++) {
                    float v = pr[i] + hasb * bias_s[jb + i];
                    o[i] = (v > 0.f) ? v : expm1f(v);
                }
                *(float4*)(cp)     = make_float4(o[0], o[1], o[2], o[3]);
                *(float4*)(cp + 4) = make_float4(o[4], o[5], o[6], o[7]);
            } else {
                float* gp = g_gates + (size_t)y * NN * GG + (size_t)mrow * GG + jb;
                float4 a0 = *(const float4*)(pr);
                float4 a1 = *(const float4*)(pr + 4);
                a0.x += bias_s[jb];     a0.y += bias_s[jb + 1];
                a0.z += bias_s[jb + 2]; a0.w += bias_s[jb + 3];
                a1.x += bias_s[jb + 4]; a1.y += bias_s[jb + 5];
                a1.z += bias_s[jb + 6]; a1.w += bias_s[jb + 7];
                *(float4*)(gp)     = a0;
                *(float4*)(gp + 4) = a1;
            }
        }
        __syncwarp();
    }
}

// ---------------- k_gate --------------------------------------------------------
__global__ void k_gate(float* __restrict__ out) {
    int idx = blockIdx.x * blockDim.x + threadIdx.x;
    if (idx >= NN * GG) return;
    const size_t S = (size_t)NN * GG;
    float rs = g_gates[idx];
    float zs = g_gates[S + idx];
    float inn = g_gates[2 * S + idx];
    float hn  = g_gates[3 * S + idx];
    float r = sigm(rs);
    float z = sigm(zs);
    float n = tanhf(inn + r * hn);
    float hv = g_hv[idx];
    float h = (1.f - z) * n + z * hv;
    out[idx] = fmaxf(h, 0.f);
}

// ---------------- launch ----------------------------------------------------------
extern "C" void kernel_launch(void* const* d_in, const int* in_sizes, int n_in,
                              void* d_out, int out_size) {
    const float* nf  = (const float*)d_in[0];
    const float* ef  = (const float*)d_in[1];
    const int*   src = (const int*)d_in[2];
    const int*   dst = (const int*)d_in[3];
    const float* Wn  = (const float*)d_in[4];
    const float* bn  = (const float*)d_in[5];
    const float* We1 = (const float*)d_in[6];
    const float* be1 = (const float*)d_in[7];
    const float* We2 = (const float*)d_in[8];
    const float* be2 = (const float*)d_in[9];
    const float* Wet = (const float*)d_in[10];
    const float* bet = (const float*)d_in[11];
    const float* Wih = (const float*)d_in[12];
    const float* bih = (const float*)d_in[13];
    const float* Whh = (const float*)d_in[14];
    const float* bhh = (const float*)d_in[15];
    float* out = (float*)d_out;

    cudaFuncSetAttribute(k_nodeproj, cudaFuncAttributeMaxDynamicSharedMemorySize, NP_SMEM * 4);
    cudaFuncSetAttribute(k_wmma<0>, cudaFuncAttributeMaxDynamicSharedMemorySize, WM_SMEM);
    cudaFuncSetAttribute(k_wmma<1>, cudaFuncAttributeMaxDynamicSharedMemorySize, WM_SMEM);

    k_init<<<(NN * GG / 4 + 255) / 256, 256>>>();
    k_packW<<<(7 * KP * KP + 255) / 256, 256>>>(Wet, Wih, Whh);
    k_nodeproj<<<(NN + 31) / 32, 256, NP_SMEM * 4>>>(nf, Wn, bn, We2, We1);
    k_edge1<<<1184, 256>>>(ef, src, dst, We1, be1, We2, be2);
    k_wmma<0><<<NTILE, 256, WM_SMEM>>>(bet, nullptr);
    k_wmma<1><<<dim3(NTILE, 4), 256, WM_SMEM>>>(bih, bhh);
    k_gate<<<(NN * GG + 255) / 256, 256>>>(out);
}

// round 17
// speedup vs baseline: 1.0711x; 1.0711x over previous
#include <cuda_runtime.h>
#include <cuda_bf16.h>
#include <mma.h>
#include <math.h>
#include <stdint.h>

using namespace nvcuda;

#define NN   25000
#define NE   500000
#define NDIM 32
#define EDIM 19
#define GG   200

// ---- tensor-GEMM geometry ---------------------------------------------------
#define NTILE 196                 // M-tiles of 128 nodes
#define KP    208                 // K padded (weight planes)
#define NT    13                  // output 16-col tiles (208)
#define APL   (128 * 24)          // smem A plane (elements)
#define BPL   (208 * 24)          // smem B plane (elements)
#define WPL   ((size_t)KP * KP)   // global W plane per slice (elements)

// ---------------- scratch (device globals) ----------------------------------
static __device__ float g_hv[NN * GG];
static __device__ float g_P[NN * GG];
static __device__ float g_q[NN];
static __device__ float g_denom[NN];
static __device__ float g_inv[NN];
static __device__ float g_s[NN * GG];
static __device__ float g_ctx[NN * GG];
static __device__ float g_gates[(size_t)4 * NN * GG];   // r-sum, z-sum, inn, hn
static __device__ __align__(128) __nv_bfloat16 g_Wpk[7 * 2 * KP * KP];

// ---------------- helpers ----------------------------------------------------
__device__ __forceinline__ float lrelu(float x) { return x > 0.f ? x : 0.01f * x; }
__device__ __forceinline__ float sigm(float x) { return 1.f / (1.f + __expf(-x)); }
__device__ __forceinline__ void bfsplit(float x, __nv_bfloat16& hi, __nv_bfloat16& lo) {
    hi = __float2bfloat16(x);
    lo = __float2bfloat16(x - __bfloat162float(hi));
}
__device__ __forceinline__ unsigned pack2(__nv_bfloat16 a, __nv_bfloat16 b) {
    return (unsigned)__bfloat16_as_ushort(a) | ((unsigned)__bfloat16_as_ushort(b) << 16);
}
// no "memory" clobber — g_s has no in-kernel readers; data-deps order values.
__device__ __forceinline__ void red4(float* p, float a, float b, float c, float d) {
    asm volatile("red.global.add.v4.f32 [%0], {%1, %2, %3, %4};"
                 :: "l"(p), "f"(a), "f"(b), "f"(c), "f"(d));
}

// ---------------- k_init (vectorized) ----------------------------------------
__global__ void k_init() {
    int idx = blockIdx.x * blockDim.x + threadIdx.x;
    if (idx < NN * GG / 4)
        ((float4*)g_s)[idx] = make_float4(0.f, 0.f, 0.f, 0.f);
    if (idx < NN) g_denom[idx] = 0.f;
}

// ---------------- k_inv ------------------------------------------------------
__global__ void k_inv() {
    int idx = blockIdx.x * blockDim.x + threadIdx.x;
    if (idx < NN) {
        float d = g_denom[idx];
        g_inv[idx] = (d > 0.f) ? (1.f / d) : 0.f;
    }
}

// ---------------- k_packW ------------------------------------------------------
__global__ void k_packW(const float* __restrict__ Wet,
                        const float* __restrict__ Wih,
                        const float* __restrict__ Whh) {
    int idx = blockIdx.x * 256 + threadIdx.x;
    if (idx >= 7 * KP * KP) return;
    int s = idx / (KP * KP);
    int rem = idx - s * (KP * KP);
    int n = rem / KP, k = rem - n * KP;
    float v = 0.f;
    if (n < GG && k < GG) {
        if (s == 0)       v = Wet[n * GG + k];
        else if (s < 4)   v = Wih[(size_t)((s - 1) * GG + n) * GG + k];
        else              v = Whh[(size_t)((s - 4) * GG + n) * GG + k];
    }
    __nv_bfloat16 hi, lo; bfsplit(v, hi, lo);
    g_Wpk[(size_t)(s * 2) * KP * KP + rem] = hi;
    g_Wpk[(size_t)(s * 2 + 1) * KP * KP + rem] = lo;
}

// ---------------- k_nodeproj ---------------------------------------------------
#define NP_WNT  0
#define NP_W1T  7296
#define NP_INS  14592
#define NP_BN   15648
#define NP_W2A  15848
#define NP_QP   16048
#define NP_SMEM 16304

__global__ void k_nodeproj(const float* __restrict__ nf,
                           const float* __restrict__ Wn,
                           const float* __restrict__ bn,
                           const float* __restrict__ We2,
                           const float* __restrict__ We1) {
    extern __shared__ float sm[];
    float* wnt  = sm + NP_WNT;
    float* w1t  = sm + NP_W1T;
    float* ins  = sm + NP_INS;
    float* bn_s = sm + NP_BN;
    float* w2a  = sm + NP_W2A;
    float* qp   = sm + NP_QP;
    float* outh = sm;
    float* outp = sm + 6432;

    int tid = threadIdx.x;
    int lane = tid & 31, grp = tid >> 5;
    int n0 = blockIdx.x * 32;

    for (int i = tid; i < GG * NDIM; i += 256) {
        int r = i >> 5, k = i & 31;
        int g = r / 25, j = r - g * 25;
        wnt[k * 228 + g * 28 + j] = Wn[i];
        w1t[k * 228 + g * 28 + j] = We1[r * 51 + k];
    }
    for (int i = tid; i < GG; i += 256) { bn_s[i] = bn[i]; w2a[i] = We2[i]; }
    for (int i = tid; i < 32 * NDIM; i += 256) {
        int n = i >> 5, k = i & 31;
        ins[k * 33 + n] = (n0 + n < NN) ? nf[(size_t)(n0 + n) * NDIM + k] : 0.f;
    }
    __syncthreads();

    float acc[28], accP[28];
#pragma unroll
    for (int j = 0; j < 28; j++) { acc[j] = (j < 25) ? bn_s[grp * 25 + j] : 0.f; accP[j] = 0.f; }

    for (int k = 0; k < NDIM; k++) {
        float x = ins[k * 33 + lane];
        const float4* wp = (const float4*)&wnt[k * 228 + grp * 28];
        const float4* pp = (const float4*)&w1t[k * 228 + grp * 28];
#pragma unroll
        for (int j4 = 0; j4 < 7; j4++) {
            float4 w = wp[j4], p = pp[j4];
            acc[j4*4+0] += x * w.x;  acc[j4*4+1] += x * w.y;
            acc[j4*4+2] += x * w.z;  acc[j4*4+3] += x * w.w;
            accP[j4*4+0] += x * p.x; accP[j4*4+1] += x * p.y;
            accP[j4*4+2] += x * p.z; accP[j4*4+3] += x * p.w;
        }
    }
    __syncthreads();

    float qdot = 0.f;
#pragma unroll
    for (int j = 0; j < 25; j++) {
        float v = lrelu(acc[j]);
        outh[lane * 201 + grp * 25 + j] = v;
        outp[lane * 201 + grp * 25 + j] = accP[j];
        qdot += v * w2a[grp * 25 + j];
    }
    qp[grp * 32 + lane] = qdot;
    __syncthreads();

    for (int i = tid; i < 32 * GG; i += 256) {
        int n = i / GG, o = i - n * GG;
        if (n0 + n < NN) {
            g_hv[(size_t)(n0 + n) * GG + o] = outh[n * 201 + o];
            g_P[(size_t)(n0 + n) * GG + o]  = outp[n * 201 + o];
        }
    }
    if (tid < 32 && n0 + tid < NN) {
        float q = 0.f;
#pragma unroll
        for (int g = 0; g < 8; g++) q += qp[g * 32 + tid];
        g_q[n0 + tid] = q;
    }
}

// ---------------- k_edge1: warp-per-edge, phase-split epilogue -----------------
#define E_NT   (NE / 32)

__global__ void __launch_bounds__(256)
k_edge1(const float* __restrict__ ef,
        const int* __restrict__ src,
        const int* __restrict__ dst,
        const float* __restrict__ We1,
        const float* __restrict__ be1,
        const float* __restrict__ We2,
        const float* __restrict__ be2) {
    __shared__ float w1s[19 * 256];
    __shared__ float b1s[256];
    __shared__ float w2bs[256];

    int tid = threadIdx.x;
    int lane = tid & 31, warp = tid >> 5;
    const unsigned FULL = 0xffffffffu;

    for (int i = tid; i < 19 * 256; i += 256) {
        int k = i >> 8, f = i & 255;
        w1s[i] = (f < GG) ? We1[f * 51 + NDIM + k] : 0.f;
    }
    for (int i = tid; i < 256; i += 256) {
        b1s[i]  = (i < GG) ? be1[i] : 0.f;
        w2bs[i] = (i < GG) ? We2[GG + i] : 0.f;
    }
    float be2v = be2[0];
    __syncthreads();

    float4 binit0 = *(const float4*)&b1s[lane * 4];
    float4 binit1 = *(const float4*)&b1s[128 + lane * 4];
    float4 w2r0   = *(const float4*)&w2bs[lane * 4];
    float4 w2r1   = *(const float4*)&w2bs[128 + lane * 4];
    bool q1ok = (lane < 18);

    for (int t = blockIdx.x; t < E_NT; t += gridDim.x) {
        int ebase = t * 32 + warp * 4;

        int sreg = 0, dreg = 0;
        if (lane < 4) { sreg = src[ebase + lane]; dreg = dst[ebase + lane]; }
        float er[4];
#pragma unroll
        for (int q = 0; q < 4; q++)
            er[q] = (lane < EDIM) ? ef[(size_t)(ebase + q) * EDIM + lane] : 0.f;

        float acc[4][8];
#pragma unroll
        for (int q = 0; q < 4; q++) {
            acc[q][0] = binit0.x; acc[q][1] = binit0.y;
            acc[q][2] = binit0.z; acc[q][3] = binit0.w;
            acc[q][4] = binit1.x; acc[q][5] = binit1.y;
            acc[q][6] = binit1.z; acc[q][7] = binit1.w;
        }

        for (int k = 0; k < EDIM; k++) {
            float4 w0 = *(const float4*)&w1s[k * 256 + lane * 4];
            float4 w1 = *(const float4*)&w1s[k * 256 + 128 + lane * 4];
#pragma unroll
            for (int q = 0; q < 4; q++) {
                float x = __shfl_sync(FULL, er[q], k);
                acc[q][0] += x * w0.x; acc[q][1] += x * w0.y;
                acc[q][2] += x * w0.z; acc[q][3] += x * w0.w;
                acc[q][4] += x * w1.x; acc[q][5] += x * w1.y;
                acc[q][6] += x * w1.z; acc[q][7] += x * w1.w;
            }
        }

        // ---- phase A: loads + he1 + logits (no global stores -> MLP across q) --
        float exq[4];
#pragma unroll
        for (int q = 0; q < 4; q++) {
            int s_q = __shfl_sync(FULL, sreg, q);
            const float* Pr = g_P + (size_t)s_q * GG;

            float4 p0 = *(const float4*)(Pr + lane * 4);
            float4 p1 = q1ok ? *(const float4*)(Pr + 128 + lane * 4)
                             : make_float4(0.f, 0.f, 0.f, 0.f);

            float v0 = lrelu(acc[q][0] + p0.x);
            float v1 = lrelu(acc[q][1] + p0.y);
            float v2 = lrelu(acc[q][2] + p0.z);
            float v3 = lrelu(acc[q][3] + p0.w);
            float v4 = lrelu(acc[q][4] + p1.x);
            float v5 = lrelu(acc[q][5] + p1.y);
            float v6 = lrelu(acc[q][6] + p1.z);
            float v7 = lrelu(acc[q][7] + p1.w);
            acc[q][0] = v0; acc[q][1] = v1; acc[q][2] = v2; acc[q][3] = v3;
            acc[q][4] = v4; acc[q][5] = v5; acc[q][6] = v6; acc[q][7] = v7;

            float p = v0 * w2r0.x + v1 * w2r0.y + v2 * w2r0.z + v3 * w2r0.w
                    + v4 * w2r1.x + v5 * w2r1.y + v6 * w2r1.z + v7 * w2r1.w;
            p += __shfl_xor_sync(FULL, p, 16);
            p += __shfl_xor_sync(FULL, p, 8);
            p += __shfl_xor_sync(FULL, p, 4);
            p += __shfl_xor_sync(FULL, p, 2);
            p += __shfl_xor_sync(FULL, p, 1);

            int d_q = __shfl_sync(FULL, dreg, q);
            float l = lrelu(be2v + g_q[d_q] + p);
            exq[q] = __expf(l);               // unnormalized softmax
        }

        // ---- phase B: atomics + scatters ---------------------------------------
#pragma unroll
        for (int q = 0; q < 4; q++) {
            int d_q = __shfl_sync(FULL, dreg, q);
            float ex = exq[q];
            if (lane == q) atomicAdd(&g_denom[d_q], ex);
            float* drow = g_s + (size_t)d_q * GG;
            red4(drow + lane * 4,
                 ex * acc[q][0], ex * acc[q][1], ex * acc[q][2], ex * acc[q][3]);
            if (q1ok)
                red4(drow + 128 + lane * 4,
                     ex * acc[q][4], ex * acc[q][5], ex * acc[q][6], ex * acc[q][7]);
        }
    }
}

// ---------------- k_wmma: double-buffered, vectorized-staging bf16-split GEMM --
// MODE 0 (grid 196):  ctx = elu(Wet @ (s*inv) + has*bet) -> g_ctx fp32
// MODE 1 (grid 196x4): y=0 r-sum K=416 [ctx;hv], y=1 z-sum K=416,
//                      y=2 inn = Wih_n@ctx, y=3 hn = Whh_n@hv
#define WAS(buf)  ((buf) * 12288)
#define WBS(buf)  (24576 + (buf) * 19968)
#define WPATCH    64512
#define WBIAS     74752
#define WM_SMEM   75584

template <int MODE>
__global__ void __launch_bounds__(256)
k_wmma(const float* __restrict__ bias_a, const float* __restrict__ bias_b) {
    extern __shared__ unsigned char smraw[];
    float* patch  = (float*)(smraw + WPATCH);
    float* bias_s = (float*)(smraw + WBIAS);

    int tid = threadIdx.x, lane = tid & 31, warp = tid >> 5;
    int tile = blockIdx.x;
    int y = (MODE == 0) ? 0 : blockIdx.y;
    int KTOT = (MODE == 0) ? 13 : ((y < 2) ? 26 : 13);

    for (int i = tid; i < KP; i += 256) {
        float b = 0.f;
        if (i < GG) {
            if (MODE == 0)      b = bias_a[i];
            else if (y == 0)    b = bias_a[i] + bias_b[i];
            else if (y == 1)    b = bias_a[GG + i] + bias_b[GG + i];
            else if (y == 2)    b = bias_a[2 * GG + i];
            else                b = bias_b[2 * GG + i];
        }
        bias_s[i] = b;
    }

    auto stage = [&](int kt, int buf) {
        int ktt = kt, slice; const float* srcA; bool use_inv = false;
        if (MODE == 0) { slice = 0; srcA = g_s; use_inv = true; }
        else if (y < 2) {
            if (kt < 13) { slice = 1 + y; srcA = g_ctx; }
            else         { slice = 4 + y; srcA = g_hv; ktt = kt - 13; }
        } else if (y == 2) { slice = 3; srcA = g_ctx; }
        else               { slice = 6; srcA = g_hv; }

        unsigned char* Asb = smraw + WAS(buf);
        unsigned char* Bsb = smraw + WBS(buf);
        const __nv_bfloat16* Wh = g_Wpk + (size_t)(slice * 2) * WPL;

        for (int i = tid; i < 512; i += 256) {
            int r = i >> 2, qd = i & 3;
            int node = tile * 128 + r;
            int kk = ktt * 16 + qd * 4;
            float4 v = make_float4(0.f, 0.f, 0.f, 0.f);
            if (node < NN && kk < GG) {
                v = *(const float4*)(srcA + (size_t)node * GG + kk);
                if (use_inv) {
                    float iv = g_inv[node];
                    v.x *= iv; v.y *= iv; v.z *= iv; v.w *= iv;
                }
            }
            __nv_bfloat16 h0, l0, h1, l1, h2, l2, h3, l3;
            bfsplit(v.x, h0, l0); bfsplit(v.y, h1, l1);
            bfsplit(v.z, h2, l2); bfsplit(v.w, h3, l3);
            uint2 hv2 = make_uint2(pack2(h0, h1), pack2(h2, h3));
            uint2 lv2 = make_uint2(pack2(l0, l1), pack2(l2, l3));
            *(uint2*)(Asb + r * 48 + qd * 8) = hv2;
            *(uint2*)(Asb + APL * 2 + r * 48 + qd * 8) = lv2;
        }
        for (int i = tid; i < 832; i += 256) {
            int n = i >> 2, q = i & 3;
            int plane = q >> 1, half = q & 1;
            const uint4* srcp = (const uint4*)((const unsigned char*)(Wh + (size_t)plane * WPL)
                                               + (size_t)n * (KP * 2) + ktt * 32 + half * 16);
            *(uint4*)(Bsb + (size_t)plane * (BPL * 2) + n * 48 + half * 16) = *srcp;
        }
    };

    wmma::fragment<wmma::accumulator, 16, 16, 16, float> acc[NT];
#pragma unroll
    for (int nt = 0; nt < NT; nt++) wmma::fill_fragment(acc[nt], 0.f);

    stage(0, 0);
    __syncthreads();

    for (int kt = 0; kt < KTOT; kt++) {
        int cur = kt & 1;
        if (kt + 1 < KTOT) stage(kt + 1, cur ^ 1);

        __nv_bfloat16* As = (__nv_bfloat16*)(smraw + WAS(cur));
        __nv_bfloat16* Bs = (__nv_bfloat16*)(smraw + WBS(cur));

        wmma::fragment<wmma::matrix_a, 16, 16, 16, __nv_bfloat16, wmma::row_major> a_hi, a_lo;
        wmma::load_matrix_sync(a_hi, As + warp * 16 * 24, 24);
        wmma::load_matrix_sync(a_lo, As + APL + warp * 16 * 24, 24);
#pragma unroll
        for (int nt = 0; nt < NT; nt++) {
            wmma::fragment<wmma::matrix_b, 16, 16, 16, __nv_bfloat16, wmma::col_major> b_hi, b_lo;
            wmma::load_matrix_sync(b_hi, Bs + nt * 16 * 24, 24);
            wmma::load_matrix_sync(b_lo, Bs + BPL + nt * 16 * 24, 24);
            wmma::mma_sync(acc[nt], a_hi, b_hi, acc[nt]);
            wmma::mma_sync(acc[nt], a_hi, b_lo, acc[nt]);
            wmma::mma_sync(acc[nt], a_lo, b_hi, acc[nt]);
        }
        __syncthreads();
    }

    float* pp = patch + warp * (16 * 20);
    int rr = lane >> 1;
    int c0 = (lane & 1) * 8;
    int mrow = tile * 128 + warp * 16 + rr;
    bool valid = mrow < NN;
    float hasb = 0.f;
    if (MODE == 0) hasb = (valid && g_inv[mrow] > 0.f) ? 1.f : 0.f;

    for (int nt = 0; nt < NT; nt++) {
        wmma::store_matrix_sync(pp, acc[nt], 20, wmma::mem_row_major);
        __syncwarp();
        int jb = nt * 16 + c0;
        if (valid && jb + 8 <= GG) {
            const float* pr = pp + rr * 20 + c0;
            if (MODE == 0) {
                float* cp = g_ctx + (size_t)mrow * GG + jb;
                float o[8];
#pragma unroll
                for (int i = 0; i < 8; i++) {
                    float v = pr[i] + hasb * bias_s[jb + i];
                    o[i] = (v > 0.f) ? v : expm1f(v);
                }
                *(float4*)(cp)     = make_float4(o[0], o[1], o[2], o[3]);
                *(float4*)(cp + 4) = make_float4(o[4], o[5], o[6], o[7]);
            } else {
                float* gp = g_gates + (size_t)y * NN * GG + (size_t)mrow * GG + jb;
                float4 a0 = *(const float4*)(pr);
                float4 a1 = *(const float4*)(pr + 4);
                a0.x += bias_s[jb];     a0.y += bias_s[jb + 1];
                a0.z += bias_s[jb + 2]; a0.w += bias_s[jb + 3];
                a1.x += bias_s[jb + 4]; a1.y += bias_s[jb + 5];
                a1.z += bias_s[jb + 6]; a1.w += bias_s[jb + 7];
                *(float4*)(gp)     = a0;
                *(float4*)(gp + 4) = a1;
            }
        }
        __syncwarp();
    }
}

// ---------------- k_gate (float4-vectorized) -----------------------------------
__global__ void k_gate(float* __restrict__ out) {
    int idx = blockIdx.x * blockDim.x + threadIdx.x;
    if (idx >= NN * GG / 4) return;
    const size_t S4 = (size_t)NN * GG / 4;
    const float4* G = (const float4*)g_gates;
    float4 rs = G[idx];
    float4 zs = G[S4 + idx];
    float4 in4 = G[2 * S4 + idx];
    float4 hn4 = G[3 * S4 + idx];
    float4 hv4 = ((const float4*)g_hv)[idx];
    float4 o;
    {
        float r = sigm(rs.x), z = sigm(zs.x);
        float n = tanhf(in4.x + r * hn4.x);
        o.x = fmaxf((1.f - z) * n + z * hv4.x, 0.f);
    }
    {
        float r = sigm(rs.y), z = sigm(zs.y);
        float n = tanhf(in4.y + r * hn4.y);
        o.y = fmaxf((1.f - z) * n + z * hv4.y, 0.f);
    }
    {
        float r = sigm(rs.z), z = sigm(zs.z);
        float n = tanhf(in4.z + r * hn4.z);
        o.z = fmaxf((1.f - z) * n + z * hv4.z, 0.f);
    }
    {
        float r = sigm(rs.w), z = sigm(zs.w);
        float n = tanhf(in4.w + r * hn4.w);
        o.w = fmaxf((1.f - z) * n + z * hv4.w, 0.f);
    }
    ((float4*)out)[idx] = o;
}

// ---------------- launch ----------------------------------------------------------
extern "C" void kernel_launch(void* const* d_in, const int* in_sizes, int n_in,
                              void* d_out, int out_size) {
    const float* nf  = (const float*)d_in[0];
    const float* ef  = (const float*)d_in[1];
    const int*   src = (const int*)d_in[2];
    const int*   dst = (const int*)d_in[3];
    const float* Wn  = (const float*)d_in[4];
    const float* bn  = (const float*)d_in[5];
    const float* We1 = (const float*)d_in[6];
    const float* be1 = (const float*)d_in[7];
    const float* We2 = (const float*)d_in[8];
    const float* be2 = (const float*)d_in[9];
    const float* Wet = (const float*)d_in[10];
    const float* bet = (const float*)d_in[11];
    const float* Wih = (const float*)d_in[12];
    const float* bih = (const float*)d_in[13];
    const float* Whh = (const float*)d_in[14];
    const float* bhh = (const float*)d_in[15];
    float* out = (float*)d_out;

    cudaFuncSetAttribute(k_nodeproj, cudaFuncAttributeMaxDynamicSharedMemorySize, NP_SMEM * 4);
    cudaFuncSetAttribute(k_wmma<0>, cudaFuncAttributeMaxDynamicSharedMemorySize, WM_SMEM);
    cudaFuncSetAttribute(k_wmma<1>, cudaFuncAttributeMaxDynamicSharedMemorySize, WM_SMEM);

    k_init<<<(NN * GG / 4 + 255) / 256, 256>>>();
    k_packW<<<(7 * KP * KP + 255) / 256, 256>>>(Wet, Wih, Whh);
    k_nodeproj<<<(NN + 31) / 32, 256, NP_SMEM * 4>>>(nf, Wn, bn, We2, We1);
    k_edge1<<<1184, 256>>>(ef, src, dst, We1, be1, We2, be2);
    k_inv<<<(NN + 255) / 256, 256>>>();
    k_wmma<0><<<NTILE, 256, WM_SMEM>>>(bet, nullptr);
    k_wmma<1><<<dim3(NTILE, 4), 256, WM_SMEM>>>(bih, bhh);
    k_gate<<<(NN * GG / 4 + 255) / 256, 256>>>(out);
}